// round 1
// baseline (speedup 1.0000x reference)
#include <cuda_runtime.h>

#define BATCH 64
#define SEQ   512
#define INP   1024
#define HID   1024
#define NBLK  128

__device__ float g_X[(size_t)SEQ * BATCH * 4 * HID];
__device__ unsigned int g_cnt = 0;
__device__ unsigned int g_epoch = 0;

__device__ __forceinline__ float sigmoidf_(float x) {
    return 1.0f / (1.0f + __expf(-x));
}

__global__ void gate_proj(const float* __restrict__ x,
                          const float* __restrict__ U0, const float* __restrict__ U1,
                          const float* __restrict__ U2, const float* __restrict__ U3,
                          const float* __restrict__ bb0, const float* __restrict__ bb1,
                          const float* __restrict__ bb2, const float* __restrict__ bb3)
{
    __shared__ float As[16][65];
    __shared__ float Bs[16][65];
    const int tid = threadIdx.x;
    const int tx = tid & 15;
    const int ty = tid >> 4;
    const int n0 = blockIdx.x * 64;
    const int m0 = blockIdx.y * 64;
    const int gate = n0 >> 10;
    const int jj0 = n0 & 1023;

    const float* U  = (gate == 0) ? U0  : (gate == 1) ? U1  : (gate == 2) ? U2  : U3;
    const float* bs = (gate == 0) ? bb0 : (gate == 1) ? bb1 : (gate == 2) ? bb2 : bb3;

    float acc[4][4] = {};

    for (int k0 = 0; k0 < INP; k0 += 16) {
        #pragma unroll
        for (int r = 0; r < 4; ++r) {
            int e = r * 256 + tid;
            int kk = e & 15, mm = e >> 4;
            As[kk][mm] = x[(size_t)(m0 + mm) * INP + k0 + kk];
        }
        #pragma unroll
        for (int r = 0; r < 4; ++r) {
            int e = r * 256 + tid;
            int nn = e & 63, kk = e >> 6;
            Bs[kk][nn] = U[(size_t)(k0 + kk) * HID + jj0 + nn];
        }
        __syncthreads();
        #pragma unroll
        for (int kk = 0; kk < 16; ++kk) {
            float a[4], b[4];
            #pragma unroll
            for (int i = 0; i < 4; ++i) a[i] = As[kk][ty * 4 + i];
            #pragma unroll
            for (int j = 0; j < 4; ++j) b[j] = Bs[kk][tx * 4 + j];
            #pragma unroll
            for (int i = 0; i < 4; ++i)
                #pragma unroll
                for (int j = 0; j < 4; ++j)
                    acc[i][j] += a[i] * b[j];
        }
        __syncthreads();
    }

    #pragma unroll
    for (int i = 0; i < 4; ++i) {
        int m = m0 + ty * 4 + i;
        int t = m & (SEQ - 1);
        int b = m >> 9;
        size_t base = ((size_t)t * BATCH + b) * 4096 + n0 + tx * 4;
        #pragma unroll
        for (int j = 0; j < 4; ++j)
            g_X[base + j] = acc[i][j] + bs[jj0 + tx * 4 + j];
    }
}

__global__ void __launch_bounds__(256, 1)
lstm_scan(const float* __restrict__ W0, const float* __restrict__ W1,
          const float* __restrict__ W2, const float* __restrict__ W3,
          float* __restrict__ out)
{
    __shared__ float hs[2][64][33];
    __shared__ float ws[2][4][8][33];

    const int tid  = threadIdx.x;
    const int slot = tid & 127;
    const int kh   = tid >> 7;
    const int jl   = slot & 7;
    const int bq   = slot >> 3;
    const int jbase = blockIdx.x * 8;
    const int j = jbase + jl;

    float* ht   = out;
    float* hseq = out + (size_t)BATCH * HID;
    float* ct   = out + (size_t)BATCH * HID + (size_t)BATCH * SEQ * HID;
    float* cseq = ct + (size_t)BATCH * HID;

    const float* W[4] = {W0, W1, W2, W3};

    float creg[4] = {0.f, 0.f, 0.f, 0.f};

    for (int t = 0; t < SEQ; ++t) {
        float acc[4][4];
        #pragma unroll
        for (int g = 0; g < 4; ++g)
            #pragma unroll
            for (int i = 0; i < 4; ++i) acc[g][i] = 0.f;

        for (int kt = 0; kt < 16; ++kt) {
            #pragma unroll
            for (int r = 0; r < 16; ++r) {
                int e = r * 256 + tid;
                int kk = e & 31, b = (e >> 5) & 63, khh = (e >> 11) & 1;
                int k = khh * 512 + kt * 32 + kk;
                float v = 0.f;
                if (t > 0) v = hseq[(size_t)b * SEQ * HID + (size_t)(t - 1) * HID + k];
                hs[khh][b][kk] = v;
            }
            #pragma unroll
            for (int r = 0; r < 8; ++r) {
                int e = r * 256 + tid;
                int jl2 = e & 7, kk = (e >> 3) & 31, g = (e >> 8) & 3, khh = (e >> 10) & 1;
                int k = khh * 512 + kt * 32 + kk;
                ws[khh][g][jl2][kk] = W[g][(size_t)k * HID + jbase + jl2];
            }
            __syncthreads();
            #pragma unroll 8
            for (int kk = 0; kk < 32; ++kk) {
                float hv[4];
                #pragma unroll
                for (int i = 0; i < 4; ++i) hv[i] = hs[kh][bq * 4 + i][kk];
                #pragma unroll
                for (int g = 0; g < 4; ++g) {
                    float wv = ws[kh][g][jl][kk];
                    #pragma unroll
                    for (int i = 0; i < 4; ++i) acc[g][i] += hv[i] * wv;
                }
            }
            __syncthreads();
        }

        float* red = &hs[0][0][0];
        if (kh == 1) {
            #pragma unroll
            for (int g = 0; g < 4; ++g)
                #pragma unroll
                for (int i = 0; i < 4; ++i)
                    red[slot * 16 + g * 4 + i] = acc[g][i];
        }
        __syncthreads();

        if (kh == 0) {
            #pragma unroll
            for (int i = 0; i < 4; ++i) {
                int b = bq * 4 + i;
                size_t xbase = ((size_t)t * BATCH + b) * 4096 + j;
                float a0 = acc[0][i] + red[slot * 16 +  0 + i] + g_X[xbase];
                float a1 = acc[1][i] + red[slot * 16 +  4 + i] + g_X[xbase + 1024];
                float a2 = acc[2][i] + red[slot * 16 +  8 + i] + g_X[xbase + 2048];
                float a3 = acc[3][i] + red[slot * 16 + 12 + i] + g_X[xbase + 3072];
                float fv = sigmoidf_(a0);
                float iv = sigmoidf_(a1);
                float ov = sigmoidf_(a2);
                float gv = tanhf(a3);
                float c = fv * creg[i] + iv * gv;
                creg[i] = c;
                float h = ov * tanhf(c);
                size_t o = (size_t)b * SEQ * HID + (size_t)t * HID + j;
                hseq[o] = h;
                cseq[o] = c;
                if (t == SEQ - 1) {
                    ht[(size_t)b * HID + j] = h;
                    ct[(size_t)b * HID + j] = c;
                }
            }
        }

        __syncthreads();
        __threadfence();
        if (tid == 0) {
            unsigned int e0 = *(volatile unsigned int*)&g_epoch;
            __threadfence();
            unsigned int a = atomicAdd(&g_cnt, 1u);
            if (a == NBLK - 1) {
                atomicExch(&g_cnt, 0u);
                __threadfence();
                atomicAdd(&g_epoch, 1u);
            } else {
                while (*(volatile unsigned int*)&g_epoch == e0) { __nanosleep(64); }
            }
        }
        __syncthreads();
    }
}

extern "C" void kernel_launch(void* const* d_in, const int* in_sizes, int n_in,
                              void* d_out, int out_size)
{
    (void)in_sizes; (void)n_in; (void)out_size;
    const float* x   = (const float*)d_in[0];
    const float* U_f = (const float*)d_in[1];
    const float* W_f = (const float*)d_in[2];
    const float* b_f = (const float*)d_in[3];
    const float* U_i = (const float*)d_in[4];
    const float* W_i = (const float*)d_in[5];
    const float* b_i = (const float*)d_in[6];
    const float* U_o = (const float*)d_in[7];
    const float* W_o = (const float*)d_in[8];
    const float* b_o = (const float*)d_in[9];
    const float* U_g = (const float*)d_in[10];
    const float* W_g = (const float*)d_in[11];
    const float* b_g = (const float*)d_in[12];
    float* out = (float*)d_out;

    dim3 grid1(4096 / 64, (BATCH * SEQ) / 64);
    gate_proj<<<grid1, 256>>>(x, U_f, U_i, U_o, U_g, b_f, b_i, b_o, b_g);
    lstm_scan<<<NBLK, 256>>>(W_f, W_i, W_o, W_g, out);
}

// round 14
// speedup vs baseline: 1.5714x; 1.5714x over previous
#include <cuda_runtime.h>

#define BATCH 64
#define SEQ   512
#define INP   1024
#define HID   1024
#define NBLK  128

__device__ float g_X[(size_t)SEQ * BATCH * 4 * HID];
__device__ unsigned int g_cnt = 0;
__device__ unsigned int g_epoch = 0;

__device__ __forceinline__ float sigmoidf_(float x) {
    return 1.0f / (1.0f + __expf(-x));
}

// ---------------- packed fp32x2 helpers (FFMA2 path, exact IEEE fp32) -------
__device__ __forceinline__ unsigned long long fma2_(unsigned long long a,
                                                    unsigned long long b,
                                                    unsigned long long c) {
    unsigned long long d;
    asm("fma.rn.f32x2 %0, %1, %2, %3;" : "=l"(d) : "l"(a), "l"(b), "l"(c));
    return d;
}
__device__ __forceinline__ unsigned long long add2_(unsigned long long a,
                                                    unsigned long long b) {
    unsigned long long d;
    asm("add.rn.f32x2 %0, %1, %2;" : "=l"(d) : "l"(a), "l"(b));
    return d;
}
__device__ __forceinline__ unsigned long long dup2_(float x) {
    unsigned long long d; unsigned int u = __float_as_uint(x);
    asm("mov.b64 %0, {%1, %2};" : "=l"(d) : "r"(u), "r"(u));
    return d;
}
__device__ __forceinline__ float2 unpk_(unsigned long long v) {
    unsigned int lo, hi;
    asm("mov.b64 {%0, %1}, %2;" : "=r"(lo), "=r"(hi) : "l"(v));
    return make_float2(__uint_as_float(lo), __uint_as_float(hi));
}

// ---------------------------------------------------------------------------
// Kernel 1: gate input projections, 128x64 tile, FFMA2 micro-tile.
//   g_X[t][b][g*1024+j] = bias_g[j] + sum_i x[b][t][i] * U_g[i][j]
// ---------------------------------------------------------------------------
__global__ void gate_proj(const float* __restrict__ x,
                          const float* __restrict__ U0, const float* __restrict__ U1,
                          const float* __restrict__ U2, const float* __restrict__ U3,
                          const float* __restrict__ bb0, const float* __restrict__ bb1,
                          const float* __restrict__ bb2, const float* __restrict__ bb3)
{
    __shared__ float As[16][130];   // [kk][mm], mm<128
    __shared__ float Bs[16][66];    // [kk][nn], nn<64
    const int tid = threadIdx.x;
    const int tx = tid & 15;        // j-group: 4 j
    const int ty = tid >> 4;        // m-group: 8 m (4 pairs)
    const int n0 = blockIdx.x * 64;
    const int m0 = blockIdx.y * 128;
    const int gate = n0 >> 10;
    const int jj0 = n0 & 1023;

    const float* U  = (gate == 0) ? U0  : (gate == 1) ? U1  : (gate == 2) ? U2  : U3;
    const float* bs = (gate == 0) ? bb0 : (gate == 1) ? bb1 : (gate == 2) ? bb2 : bb3;

    unsigned long long acc[4][4];   // [m-pair p][j]
    #pragma unroll
    for (int p = 0; p < 4; ++p)
        #pragma unroll
        for (int j = 0; j < 4; ++j) acc[p][j] = 0ull;

    for (int k0 = 0; k0 < INP; k0 += 16) {
        #pragma unroll
        for (int r = 0; r < 8; ++r) {            // A: 2048 elems
            int e = r * 256 + tid;
            int kk = e & 15, mm = e >> 4;
            As[kk][mm] = x[(size_t)(m0 + mm) * INP + k0 + kk];
        }
        #pragma unroll
        for (int r = 0; r < 4; ++r) {            // B: 1024 elems
            int e = r * 256 + tid;
            int nn = e & 63, kk = e >> 6;
            Bs[kk][nn] = U[(size_t)(k0 + kk) * HID + jj0 + nn];
        }
        __syncthreads();
        #pragma unroll
        for (int kk = 0; kk < 16; ++kk) {
            unsigned long long a2[4];
            #pragma unroll
            for (int p = 0; p < 4; ++p)
                a2[p] = *(const unsigned long long*)&As[kk][ty * 8 + 2 * p];
            #pragma unroll
            for (int j = 0; j < 4; ++j) {
                unsigned long long bd = dup2_(Bs[kk][tx * 4 + j]);
                #pragma unroll
                for (int p = 0; p < 4; ++p)
                    acc[p][j] = fma2_(a2[p], bd, acc[p][j]);
            }
        }
        __syncthreads();
    }

    float b0 = bs[jj0 + tx * 4 + 0];
    float b1 = bs[jj0 + tx * 4 + 1];
    float b2 = bs[jj0 + tx * 4 + 2];
    float b3 = bs[jj0 + tx * 4 + 3];

    #pragma unroll
    for (int p = 0; p < 4; ++p) {
        float2 u0 = unpk_(acc[p][0]);
        float2 u1 = unpk_(acc[p][1]);
        float2 u2 = unpk_(acc[p][2]);
        float2 u3 = unpk_(acc[p][3]);
        int row0 = m0 + ty * 8 + 2 * p;
        #pragma unroll
        for (int h = 0; h < 2; ++h) {
            int row = row0 + h;
            int t = row & (SEQ - 1);
            int b = row >> 9;
            float4 o;
            o.x = (h ? u0.y : u0.x) + b0;
            o.y = (h ? u1.y : u1.x) + b1;
            o.z = (h ? u2.y : u2.x) + b2;
            o.w = (h ? u3.y : u3.x) + b3;
            *(float4*)&g_X[((size_t)t * BATCH + b) * 4096 + n0 + tx * 4] = o;
        }
    }
}

// ---------------------------------------------------------------------------
// Kernel 2: persistent recurrent scan, W resident in smem, FFMA2 inner loop.
// 128 blocks x 256 threads. Block owns 8 j-columns x 4 gates x 64 batches.
// Thread map: jp = tid&3 (j-pair), bq = (tid>>2)&15 (4 batches), ks = tid>>6
// (k-split 4, 256 k each). Thread accumulates 2j x 4g x 4b = 32 outputs as
// 16 f32x2 accumulators. Reduction + elementwise spread over all 256 threads;
// cell state c lives in registers of fixed owner threads (tid -> (b,j-pair)).
//
// Dynamic smem (floats):
//   ws     [0, 32768)            : W slice [4][1024][8]       128 KB
//   hstage [32768, 41088)        : h chunk [64][130]          33.3 KB (aliased by red)
//   act    [41088, 43136)        : activations, 1024 u64       8 KB
// ---------------------------------------------------------------------------
#define H_STRIDE 130
#define SCAN_SMEM_FLOATS (32768 + 64 * H_STRIDE + 2048)
#define SCAN_SMEM_BYTES  (SCAN_SMEM_FLOATS * 4)

__global__ void __launch_bounds__(256, 1)
lstm_scan(const float* __restrict__ W0, const float* __restrict__ W1,
          const float* __restrict__ W2, const float* __restrict__ W3,
          float* __restrict__ out)
{
    extern __shared__ float sm[];
    float* ws = sm;                                             // [4][1024][8]
    float* hstage = sm + 32768;                                 // [64][130]
    unsigned long long* red = (unsigned long long*)(sm + 32768);// alias hstage: [4][1024] u64
    unsigned long long* act = (unsigned long long*)(sm + 32768 + 64 * H_STRIDE); // [1024] u64

    const int tid = threadIdx.x;
    const int jp = tid & 3;
    const int bq = (tid >> 2) & 15;
    const int ks = tid >> 6;
    const int jbase = blockIdx.x * 8;

    // staging map: e = r*256+tid -> b = r*8 + (tid>>5), kq = tid&31
    const int stg_b = tid >> 5;
    const int stg_kq = tid & 31;
    const int stg_ks = stg_kq >> 3;
    const int stg_kk = (stg_kq & 7) * 4;
    const int stg_c  = stg_ks * 32 + stg_kk;          // hstage column
    const int stg_k0 = stg_ks * 256 + stg_kk;         // global-k base (+ kt*32)

    float* ht   = out;
    float* hseq = out + (size_t)BATCH * HID;
    float* ct   = out + (size_t)BATCH * HID + (size_t)BATCH * SEQ * HID;
    float* cseq = ct + (size_t)BATCH * HID;

    const float* Wg[4] = {W0, W1, W2, W3};

    // Load W slice once: ws[g][k][jl]
    for (int r = 0; r < 128; ++r) {
        int e = r * 256 + tid;
        int jl = e & 7, k = (e >> 3) & 1023, g = e >> 13;
        ws[e] = Wg[g][(size_t)k * HID + jbase + jl];
    }

    // cell state: thread owns (b3 = tid>>2, j-pair jp3 = tid&3)
    const int b3 = tid >> 2;
    const int j3 = jbase + (tid & 3) * 2;
    float c0 = 0.f, c1 = 0.f;

    for (int t = 0; t < SEQ; ++t) {
        unsigned long long acc[4][4];   // [g][i(batch)]
        #pragma unroll
        for (int g = 0; g < 4; ++g)
            #pragma unroll
            for (int i = 0; i < 4; ++i) acc[g][i] = 0ull;

        // prefetch chunk kt=0
        float4 v[8];
        if (t > 0) {
            #pragma unroll
            for (int r = 0; r < 8; ++r)
                v[r] = *(const float4*)&hseq[(size_t)(r * 8 + stg_b) * SEQ * HID +
                                             (size_t)(t - 1) * HID + stg_k0];
        } else {
            #pragma unroll
            for (int r = 0; r < 8; ++r) v[r] = make_float4(0.f, 0.f, 0.f, 0.f);
        }

        for (int kt = 0; kt < 8; ++kt) {
            __syncthreads();   // prior consumers of hstage done
            #pragma unroll
            for (int r = 0; r < 8; ++r) {
                int idx = (r * 8 + stg_b) * H_STRIDE + stg_c;
                *(float2*)&hstage[idx]     = make_float2(v[r].x, v[r].y);
                *(float2*)&hstage[idx + 2] = make_float2(v[r].z, v[r].w);
            }
            if (kt < 7) {       // prefetch next chunk; latency hidden by compute
                if (t > 0) {
                    #pragma unroll
                    for (int r = 0; r < 8; ++r)
                        v[r] = *(const float4*)&hseq[(size_t)(r * 8 + stg_b) * SEQ * HID +
                                                     (size_t)(t - 1) * HID + stg_k0 + (kt + 1) * 32];
                }
            }
            __syncthreads();   // hstage chunk ready

            const float* h0r = hstage + (bq * 4 + 0) * H_STRIDE + ks * 32;
            const float* h1r = hstage + (bq * 4 + 1) * H_STRIDE + ks * 32;
            const float* h2r = hstage + (bq * 4 + 2) * H_STRIDE + ks * 32;
            const float* h3r = hstage + (bq * 4 + 3) * H_STRIDE + ks * 32;
            const float* wp0 = ws + ((0 << 10) + (ks << 8) + (kt << 5)) * 8 + (jp << 1);
            const float* wp1 = ws + ((1 << 10) + (ks << 8) + (kt << 5)) * 8 + (jp << 1);
            const float* wp2 = ws + ((2 << 10) + (ks << 8) + (kt << 5)) * 8 + (jp << 1);
            const float* wp3 = ws + ((3 << 10) + (ks << 8) + (kt << 5)) * 8 + (jp << 1);

            #pragma unroll 8
            for (int kk = 0; kk < 32; ++kk) {
                unsigned long long hd0 = dup2_(h0r[kk]);
                unsigned long long hd1 = dup2_(h1r[kk]);
                unsigned long long hd2 = dup2_(h2r[kk]);
                unsigned long long hd3 = dup2_(h3r[kk]);
                unsigned long long w0 = *(const unsigned long long*)(wp0 + kk * 8);
                unsigned long long w1 = *(const unsigned long long*)(wp1 + kk * 8);
                unsigned long long w2 = *(const unsigned long long*)(wp2 + kk * 8);
                unsigned long long w3 = *(const unsigned long long*)(wp3 + kk * 8);
                acc[0][0] = fma2_(hd0, w0, acc[0][0]);
                acc[0][1] = fma2_(hd1, w0, acc[0][1]);
                acc[0][2] = fma2_(hd2, w0, acc[0][2]);
                acc[0][3] = fma2_(hd3, w0, acc[0][3]);
                acc[1][0] = fma2_(hd0, w1, acc[1][0]);
                acc[1][1] = fma2_(hd1, w1, acc[1][1]);
                acc[1][2] = fma2_(hd2, w1, acc[1][2]);
                acc[1][3] = fma2_(hd3, w1, acc[1][3]);
                acc[2][0] = fma2_(hd0, w2, acc[2][0]);
                acc[2][1] = fma2_(hd1, w2, acc[2][1]);
                acc[2][2] = fma2_(hd2, w2, acc[2][2]);
                acc[2][3] = fma2_(hd3, w2, acc[2][3]);
                acc[3][0] = fma2_(hd0, w3, acc[3][0]);
                acc[3][1] = fma2_(hd1, w3, acc[3][1]);
                acc[3][2] = fma2_(hd2, w3, acc[3][2]);
                acc[3][3] = fma2_(hd3, w3, acc[3][3]);
            }
        }

        __syncthreads();   // compute done before red (aliases hstage) is written

        // R1: write partial sums. po = ((b*4)+g)*4 + jp, b = bq*4+i
        #pragma unroll
        for (int g = 0; g < 4; ++g)
            #pragma unroll
            for (int i = 0; i < 4; ++i)
                red[ks * 1024 + (((bq * 4 + i) * 4 + g) * 4) + jp] = acc[g][i];
        __syncthreads();

        // R2: sum k-splits, add x-projection, activate. thread -> (g2, b2), 4 j-pairs
        {
            const int g2 = tid & 3;
            const int b2 = tid >> 2;
            #pragma unroll
            for (int q = 0; q < 4; ++q) {
                int po = tid * 4 + q;
                unsigned long long s = red[po];
                s = add2_(s, red[1024 + po]);
                s = add2_(s, red[2048 + po]);
                s = add2_(s, red[3072 + po]);
                float2 xv = *(const float2*)&g_X[((size_t)t * BATCH + b2) * 4096 +
                                                 g2 * 1024 + jbase + q * 2];
                float2 sv = unpk_(s);
                float s0 = sv.x + xv.x;
                float s1 = sv.y + xv.y;
                float a0, a1;
                if (g2 < 3) { a0 = sigmoidf_(s0); a1 = sigmoidf_(s1); }
                else        { a0 = tanhf(s0);     a1 = tanhf(s1); }
                unsigned long long pk;
                unsigned int u0 = __float_as_uint(a0), u1 = __float_as_uint(a1);
                asm("mov.b64 %0, {%1, %2};" : "=l"(pk) : "r"(u0), "r"(u1));
                act[po] = pk;
            }
        }
        __syncthreads();

        // R3: cell update. thread owns (b3, j-pair)
        {
            float2 fv = unpk_(act[(b3 * 4 + 0) * 4 + (tid & 3)]);
            float2 iv = unpk_(act[(b3 * 4 + 1) * 4 + (tid & 3)]);
            float2 ov = unpk_(act[(b3 * 4 + 2) * 4 + (tid & 3)]);
            float2 gv = unpk_(act[(b3 * 4 + 3) * 4 + (tid & 3)]);
            c0 = fv.x * c0 + iv.x * gv.x;
            c1 = fv.y * c1 + iv.y * gv.y;
            float h0 = ov.x * tanhf(c0);
            float h1 = ov.y * tanhf(c1);
            size_t o = (size_t)b3 * SEQ * HID + (size_t)t * HID + j3;
            *(float2*)&hseq[o] = make_float2(h0, h1);
            *(float2*)&cseq[o] = make_float2(c0, c1);
            if (t == SEQ - 1) {
                *(float2*)&ht[(size_t)b3 * HID + j3] = make_float2(h0, h1);
                *(float2*)&ct[(size_t)b3 * HID + j3] = make_float2(c0, c1);
            }
        }

        // grid barrier: h(t) visible to all blocks before step t+1
        __syncthreads();
        __threadfence();
        if (tid == 0) {
            unsigned int e0 = *(volatile unsigned int*)&g_epoch;
            __threadfence();
            unsigned int a = atomicAdd(&g_cnt, 1u);
            if (a == NBLK - 1) {
                atomicExch(&g_cnt, 0u);
                __threadfence();
                atomicAdd(&g_epoch, 1u);
            } else {
                while (*(volatile unsigned int*)&g_epoch == e0) { __nanosleep(64); }
            }
        }
        __syncthreads();
    }
}

extern "C" void kernel_launch(void* const* d_in, const int* in_sizes, int n_in,
                              void* d_out, int out_size)
{
    (void)in_sizes; (void)n_in; (void)out_size;
    const float* x   = (const float*)d_in[0];
    const float* U_f = (const float*)d_in[1];
    const float* W_f = (const float*)d_in[2];
    const float* b_f = (const float*)d_in[3];
    const float* U_i = (const float*)d_in[4];
    const float* W_i = (const float*)d_in[5];
    const float* b_i = (const float*)d_in[6];
    const float* U_o = (const float*)d_in[7];
    const float* W_o = (const float*)d_in[8];
    const float* b_o = (const float*)d_in[9];
    const float* U_g = (const float*)d_in[10];
    const float* W_g = (const float*)d_in[11];
    const float* b_g = (const float*)d_in[12];
    float* out = (float*)d_out;

    cudaFuncSetAttribute(lstm_scan, cudaFuncAttributeMaxDynamicSharedMemorySize,
                         SCAN_SMEM_BYTES);

    dim3 grid1(4096 / 64, (BATCH * SEQ) / 128);   // (64, 256)
    gate_proj<<<grid1, 256>>>(x, U_f, U_i, U_o, U_g, b_f, b_i, b_o, b_g);
    lstm_scan<<<NBLK, 256, SCAN_SMEM_BYTES>>>(W_f, W_i, W_o, W_g, out);
}

// round 16
// speedup vs baseline: 1.5790x; 1.0049x over previous
#include <cuda_runtime.h>

#define BATCH 64
#define SEQ   512
#define INP   1024
#define HID   1024
#define NBLK  128
#define THREADS 512

__device__ float g_X[(size_t)SEQ * BATCH * 4 * HID];
__device__ unsigned int g_cnt = 0;
__device__ unsigned int g_epoch = 0;

__device__ __forceinline__ float sigmoidf_(float x) {
    return 1.0f / (1.0f + __expf(-x));
}

// ---------------- packed fp32x2 helpers (FFMA2 path, exact IEEE fp32) -------
__device__ __forceinline__ unsigned long long fma2_(unsigned long long a,
                                                    unsigned long long b,
                                                    unsigned long long c) {
    unsigned long long d;
    asm("fma.rn.f32x2 %0, %1, %2, %3;" : "=l"(d) : "l"(a), "l"(b), "l"(c));
    return d;
}
__device__ __forceinline__ unsigned long long add2_(unsigned long long a,
                                                    unsigned long long b) {
    unsigned long long d;
    asm("add.rn.f32x2 %0, %1, %2;" : "=l"(d) : "l"(a), "l"(b));
    return d;
}
__device__ __forceinline__ unsigned long long dup2_(float x) {
    unsigned long long d; unsigned int u = __float_as_uint(x);
    asm("mov.b64 %0, {%1, %2};" : "=l"(d) : "r"(u), "r"(u));
    return d;
}
__device__ __forceinline__ float2 unpk_(unsigned long long v) {
    unsigned int lo, hi;
    asm("mov.b64 {%0, %1}, %2;" : "=r"(lo), "=r"(hi) : "l"(v));
    return make_float2(__uint_as_float(lo), __uint_as_float(hi));
}

// ---------------------------------------------------------------------------
// Kernel 1: gate input projections, 128x64 tile, FFMA2 micro-tile. UNCHANGED.
// ---------------------------------------------------------------------------
__global__ void gate_proj(const float* __restrict__ x,
                          const float* __restrict__ U0, const float* __restrict__ U1,
                          const float* __restrict__ U2, const float* __restrict__ U3,
                          const float* __restrict__ bb0, const float* __restrict__ bb1,
                          const float* __restrict__ bb2, const float* __restrict__ bb3)
{
    __shared__ float As[16][130];
    __shared__ float Bs[16][66];
    const int tid = threadIdx.x;
    const int tx = tid & 15;
    const int ty = tid >> 4;
    const int n0 = blockIdx.x * 64;
    const int m0 = blockIdx.y * 128;
    const int gate = n0 >> 10;
    const int jj0 = n0 & 1023;

    const float* U  = (gate == 0) ? U0  : (gate == 1) ? U1  : (gate == 2) ? U2  : U3;
    const float* bs = (gate == 0) ? bb0 : (gate == 1) ? bb1 : (gate == 2) ? bb2 : bb3;

    unsigned long long acc[4][4];
    #pragma unroll
    for (int p = 0; p < 4; ++p)
        #pragma unroll
        for (int j = 0; j < 4; ++j) acc[p][j] = 0ull;

    for (int k0 = 0; k0 < INP; k0 += 16) {
        #pragma unroll
        for (int r = 0; r < 8; ++r) {
            int e = r * 256 + tid;
            int kk = e & 15, mm = e >> 4;
            As[kk][mm] = x[(size_t)(m0 + mm) * INP + k0 + kk];
        }
        #pragma unroll
        for (int r = 0; r < 4; ++r) {
            int e = r * 256 + tid;
            int nn = e & 63, kk = e >> 6;
            Bs[kk][nn] = U[(size_t)(k0 + kk) * HID + jj0 + nn];
        }
        __syncthreads();
        #pragma unroll
        for (int kk = 0; kk < 16; ++kk) {
            unsigned long long a2[4];
            #pragma unroll
            for (int p = 0; p < 4; ++p)
                a2[p] = *(const unsigned long long*)&As[kk][ty * 8 + 2 * p];
            #pragma unroll
            for (int j = 0; j < 4; ++j) {
                unsigned long long bd = dup2_(Bs[kk][tx * 4 + j]);
                #pragma unroll
                for (int p = 0; p < 4; ++p)
                    acc[p][j] = fma2_(a2[p], bd, acc[p][j]);
            }
        }
        __syncthreads();
    }

    float b0 = bs[jj0 + tx * 4 + 0];
    float b1 = bs[jj0 + tx * 4 + 1];
    float b2 = bs[jj0 + tx * 4 + 2];
    float b3 = bs[jj0 + tx * 4 + 3];

    #pragma unroll
    for (int p = 0; p < 4; ++p) {
        float2 u0 = unpk_(acc[p][0]);
        float2 u1 = unpk_(acc[p][1]);
        float2 u2 = unpk_(acc[p][2]);
        float2 u3 = unpk_(acc[p][3]);
        int row0 = m0 + ty * 8 + 2 * p;
        #pragma unroll
        for (int h = 0; h < 2; ++h) {
            int row = row0 + h;
            int t = row & (SEQ - 1);
            int b = row >> 9;
            float4 o;
            o.x = (h ? u0.y : u0.x) + b0;
            o.y = (h ? u1.y : u1.x) + b1;
            o.z = (h ? u2.y : u2.x) + b2;
            o.w = (h ? u3.y : u3.x) + b3;
            *(float4*)&g_X[((size_t)t * BATCH + b) * 4096 + n0 + tx * 4] = o;
        }
    }
}

// ---------------------------------------------------------------------------
// Kernel 2: persistent recurrent scan, 512 THREADS (16 warps/SM).
// Same micro-tile as the measured 17.3ms kernel (4 w LDS.64 + 4 h LDS ->
// 16 FFMA2 per kk), k-split 8 (ks = tid>>6, 128 k each). Two-phase k-split
// reduction: ks>=4 spill 4x1024 u64 (32 KB, fits hstage alias), ks<4 fold.
//
// Dynamic smem (floats):
//   ws     [0, 32768)            : W slice [4][1024][8]       128 KB
//   hstage [32768, 41088)        : h chunk [64][130]          33.3 KB (aliased by red)
//   act    [41088, 43136)        : activations, 1024 u64       8 KB
// ---------------------------------------------------------------------------
#define H_STRIDE 130
#define SCAN_SMEM_FLOATS (32768 + 64 * H_STRIDE + 2048)
#define SCAN_SMEM_BYTES  (SCAN_SMEM_FLOATS * 4)

__global__ void __launch_bounds__(THREADS, 1)
lstm_scan(const float* __restrict__ W0, const float* __restrict__ W1,
          const float* __restrict__ W2, const float* __restrict__ W3,
          float* __restrict__ out)
{
    extern __shared__ float sm[];
    float* ws = sm;                                             // [4][1024][8]
    float* hstage = sm + 32768;                                 // [64][130]
    unsigned long long* red = (unsigned long long*)(sm + 32768);// alias hstage: [4][1024] u64
    unsigned long long* act = (unsigned long long*)(sm + 32768 + 64 * H_STRIDE); // [1024] u64

    const int tid = threadIdx.x;
    const int slot = tid & 63;
    const int jp = slot & 3;
    const int bq = slot >> 2;          // 0..15, 4 batches each
    const int ks = tid >> 6;           // 0..7, k-cols [ks*16, ks*16+16) per chunk
    const int jbase = blockIdx.x * 8;

    // staging map: float4 slot s = r*512 + tid -> b = r*16 + (tid>>5), cq = tid&31
    const int stg_b0 = tid >> 5;       // + r*16
    const int stg_cq = tid & 31;       // float4 column group; col = cq*4

    float* ht   = out;
    float* hseq = out + (size_t)BATCH * HID;
    float* ct   = out + (size_t)BATCH * HID + (size_t)BATCH * SEQ * HID;
    float* cseq = ct + (size_t)BATCH * HID;

    const float* Wg[4] = {W0, W1, W2, W3};

    // Load W slice once: ws[g][k][jl] (32768 elems / 512 threads = 64 iters)
    for (int r = 0; r < 64; ++r) {
        int e = r * 512 + tid;
        int jl = e & 7, k = (e >> 3) & 1023, g = e >> 13;
        ws[e] = Wg[g][(size_t)k * HID + jbase + jl];
    }

    // cell state owners: tid < 256, (b3 = tid>>2, j-pair tid&3)
    const int b3 = tid >> 2;
    const int j3 = jbase + (tid & 3) * 2;
    float c0 = 0.f, c1 = 0.f;

    for (int t = 0; t < SEQ; ++t) {
        unsigned long long acc[4][4];   // [g][i(batch)]
        #pragma unroll
        for (int g = 0; g < 4; ++g)
            #pragma unroll
            for (int i = 0; i < 4; ++i) acc[g][i] = 0ull;

        // prefetch chunk kt=0 (4 float4 per thread)
        float4 v[4];
        if (t > 0) {
            #pragma unroll
            for (int r = 0; r < 4; ++r)
                v[r] = *(const float4*)&hseq[(size_t)(r * 16 + stg_b0) * SEQ * HID +
                                             (size_t)(t - 1) * HID + stg_cq * 4];
        } else {
            #pragma unroll
            for (int r = 0; r < 4; ++r) v[r] = make_float4(0.f, 0.f, 0.f, 0.f);
        }

        for (int kt = 0; kt < 8; ++kt) {
            __syncthreads();   // prior consumers of hstage done
            #pragma unroll
            for (int r = 0; r < 4; ++r) {
                int idx = (r * 16 + stg_b0) * H_STRIDE + stg_cq * 4;
                *(float2*)&hstage[idx]     = make_float2(v[r].x, v[r].y);
                *(float2*)&hstage[idx + 2] = make_float2(v[r].z, v[r].w);
            }
            if (kt < 7) {       // prefetch next chunk
                if (t > 0) {
                    #pragma unroll
                    for (int r = 0; r < 4; ++r)
                        v[r] = *(const float4*)&hseq[(size_t)(r * 16 + stg_b0) * SEQ * HID +
                                                     (size_t)(t - 1) * HID + (kt + 1) * 128 + stg_cq * 4];
                }
            }
            __syncthreads();   // hstage chunk ready

            const float* h0r = hstage + (bq * 4 + 0) * H_STRIDE + ks * 16;
            const float* h1r = hstage + (bq * 4 + 1) * H_STRIDE + ks * 16;
            const float* h2r = hstage + (bq * 4 + 2) * H_STRIDE + ks * 16;
            const float* h3r = hstage + (bq * 4 + 3) * H_STRIDE + ks * 16;
            // k = kt*128 + ks*16 + kk ; ws offset = (g*1024 + k)*8 + jp*2
            const float* wp0 = ws + ((0 << 10) + (kt << 7) + (ks << 4)) * 8 + (jp << 1);
            const float* wp1 = ws + ((1 << 10) + (kt << 7) + (ks << 4)) * 8 + (jp << 1);
            const float* wp2 = ws + ((2 << 10) + (kt << 7) + (ks << 4)) * 8 + (jp << 1);
            const float* wp3 = ws + ((3 << 10) + (kt << 7) + (ks << 4)) * 8 + (jp << 1);

            #pragma unroll 8
            for (int kk = 0; kk < 16; ++kk) {
                unsigned long long hd0 = dup2_(h0r[kk]);
                unsigned long long hd1 = dup2_(h1r[kk]);
                unsigned long long hd2 = dup2_(h2r[kk]);
                unsigned long long hd3 = dup2_(h3r[kk]);
                unsigned long long w0 = *(const unsigned long long*)(wp0 + kk * 8);
                unsigned long long w1 = *(const unsigned long long*)(wp1 + kk * 8);
                unsigned long long w2 = *(const unsigned long long*)(wp2 + kk * 8);
                unsigned long long w3 = *(const unsigned long long*)(wp3 + kk * 8);
                acc[0][0] = fma2_(hd0, w0, acc[0][0]);
                acc[0][1] = fma2_(hd1, w0, acc[0][1]);
                acc[0][2] = fma2_(hd2, w0, acc[0][2]);
                acc[0][3] = fma2_(hd3, w0, acc[0][3]);
                acc[1][0] = fma2_(hd0, w1, acc[1][0]);
                acc[1][1] = fma2_(hd1, w1, acc[1][1]);
                acc[1][2] = fma2_(hd2, w1, acc[1][2]);
                acc[1][3] = fma2_(hd3, w1, acc[1][3]);
                acc[2][0] = fma2_(hd0, w2, acc[2][0]);
                acc[2][1] = fma2_(hd1, w2, acc[2][1]);
                acc[2][2] = fma2_(hd2, w2, acc[2][2]);
                acc[2][3] = fma2_(hd3, w2, acc[2][3]);
                acc[3][0] = fma2_(hd0, w3, acc[3][0]);
                acc[3][1] = fma2_(hd1, w3, acc[3][1]);
                acc[3][2] = fma2_(hd2, w3, acc[3][2]);
                acc[3][3] = fma2_(hd3, w3, acc[3][3]);
            }
        }

        __syncthreads();   // all compute done before red (aliases hstage) is written

        // R1 phase A: upper 4 k-splits spill partials. po = ((b*4)+g)*4 + jp
        if (ks >= 4) {
            #pragma unroll
            for (int g = 0; g < 4; ++g)
                #pragma unroll
                for (int i = 0; i < 4; ++i)
                    red[(ks - 4) * 1024 + (((bq * 4 + i) * 4 + g) * 4) + jp] = acc[g][i];
        }
        __syncthreads();

        // R1 phase B: lower 4 k-splits fold partner in and write
        if (ks < 4) {
            #pragma unroll
            for (int g = 0; g < 4; ++g)
                #pragma unroll
                for (int i = 0; i < 4; ++i) {
                    int po = ks * 1024 + (((bq * 4 + i) * 4 + g) * 4) + jp;
                    red[po] = add2_(acc[g][i], red[po]);
                }
        }
        __syncthreads();

        // R2: sum 4 partials, add x-projection, activate. 2 outputs/thread.
        {
            #pragma unroll
            for (int q = 0; q < 2; ++q) {
                int po = tid * 2 + q;
                int b2 = po >> 4;
                int g2 = (po >> 2) & 3;
                int jpq = po & 3;
                unsigned long long s = red[po];
                s = add2_(s, red[1024 + po]);
                s = add2_(s, red[2048 + po]);
                s = add2_(s, red[3072 + po]);
                float2 xv = *(const float2*)&g_X[((size_t)t * BATCH + b2) * 4096 +
                                                 g2 * 1024 + jbase + jpq * 2];
                float2 sv = unpk_(s);
                float s0 = sv.x + xv.x;
                float s1 = sv.y + xv.y;
                float a0, a1;
                if (g2 < 3) { a0 = sigmoidf_(s0); a1 = sigmoidf_(s1); }
                else        { a0 = tanhf(s0);     a1 = tanhf(s1); }
                unsigned long long pk;
                unsigned int u0 = __float_as_uint(a0), u1 = __float_as_uint(a1);
                asm("mov.b64 %0, {%1, %2};" : "=l"(pk) : "r"(u0), "r"(u1));
                act[po] = pk;
            }
        }
        __syncthreads();

        // R3: cell update. owners tid < 256: (b3, j-pair)
        if (tid < 256) {
            float2 fv = unpk_(act[(b3 * 4 + 0) * 4 + (tid & 3)]);
            float2 iv = unpk_(act[(b3 * 4 + 1) * 4 + (tid & 3)]);
            float2 ov = unpk_(act[(b3 * 4 + 2) * 4 + (tid & 3)]);
            float2 gv = unpk_(act[(b3 * 4 + 3) * 4 + (tid & 3)]);
            c0 = fv.x * c0 + iv.x * gv.x;
            c1 = fv.y * c1 + iv.y * gv.y;
            float h0 = ov.x * tanhf(c0);
            float h1 = ov.y * tanhf(c1);
            size_t o = (size_t)b3 * SEQ * HID + (size_t)t * HID + j3;
            *(float2*)&hseq[o] = make_float2(h0, h1);
            *(float2*)&cseq[o] = make_float2(c0, c1);
            if (t == SEQ - 1) {
                *(float2*)&ht[(size_t)b3 * HID + j3] = make_float2(h0, h1);
                *(float2*)&ct[(size_t)b3 * HID + j3] = make_float2(c0, c1);
            }
        }

        // grid barrier: h(t) visible to all blocks before step t+1
        __syncthreads();
        __threadfence();
        if (tid == 0) {
            unsigned int e0 = *(volatile unsigned int*)&g_epoch;
            __threadfence();
            unsigned int a = atomicAdd(&g_cnt, 1u);
            if (a == NBLK - 1) {
                atomicExch(&g_cnt, 0u);
                __threadfence();
                atomicAdd(&g_epoch, 1u);
            } else {
                while (*(volatile unsigned int*)&g_epoch == e0) { __nanosleep(64); }
            }
        }
        __syncthreads();
    }
}

extern "C" void kernel_launch(void* const* d_in, const int* in_sizes, int n_in,
                              void* d_out, int out_size)
{
    (void)in_sizes; (void)n_in; (void)out_size;
    const float* x   = (const float*)d_in[0];
    const float* U_f = (const float*)d_in[1];
    const float* W_f = (const float*)d_in[2];
    const float* b_f = (const float*)d_in[3];
    const float* U_i = (const float*)d_in[4];
    const float* W_i = (const float*)d_in[5];
    const float* b_i = (const float*)d_in[6];
    const float* U_o = (const float*)d_in[7];
    const float* W_o = (const float*)d_in[8];
    const float* b_o = (const float*)d_in[9];
    const float* U_g = (const float*)d_in[10];
    const float* W_g = (const float*)d_in[11];
    const float* b_g = (const float*)d_in[12];
    float* out = (float*)d_out;

    cudaFuncSetAttribute(lstm_scan, cudaFuncAttributeMaxDynamicSharedMemorySize,
                         SCAN_SMEM_BYTES);

    dim3 grid1(4096 / 64, (BATCH * SEQ) / 128);   // (64, 256)
    gate_proj<<<grid1, 256>>>(x, U_f, U_i, U_o, U_g, b_f, b_i, b_o, b_g);
    lstm_scan<<<NBLK, THREADS, SCAN_SMEM_BYTES>>>(W_f, W_i, W_o, W_g, out);
}